// round 9
// baseline (speedup 1.0000x reference)
#include <cuda_runtime.h>
#include <cuda_bf16.h>

#define VSA_N        2048
#define VSA_BLK      448   // 14 warps
#define VSA_BLKS_PB  148   // blocks per batch -> grid 592 = 4 waves-worth/SM exactly
// rows per block: first 124 blocks get 14 rows, last 24 get 13 (124*14+24*13=2048)

// ---------------------------------------------------------------------------
// Single fused kernel. grid = (148, B), 448 threads (14 warps).
// Balanced launch: 592 blocks == 4 * 148 SMs -> every SM holds exactly 4
// blocks in one wave (the 512-block config left 80 SMs with 3 blocks and 68
// with 4 -> 13.5% critical-path imbalance, visible as occ=63.7%).
//
// Phase A: block-redundant means of q,k,v for its batch (L2-resident).
// Phase B: stage k' = (k - mk) * c1 as float4 (xyz, |k'|^2), c1 = log2e/sqrt(N).
// Phase C: hot loop, one row per warp. ALGEBRA:
//            T_i = q_i x (sum_j e_ij k_j)     (cross is bilinear)
//            |q x k|^2 = |q|^2|k|^2 - (q.k)^2 (Lagrange)
//          per pair: 3 FMA dot + 2 FMA n2 + FMNMX + MUFU sqrt + MUFU ex2 +
//          4 accum FMA + 1 LDS.128.
// Phase D: warp reduce (Z, W), epilogue cross products on lane 0.
// ---------------------------------------------------------------------------
__global__ __launch_bounds__(VSA_BLK, 4)
void vsa_fused_kernel(const float* __restrict__ q,
                      const float* __restrict__ k,
                      const float* __restrict__ v,
                      float* __restrict__ out) {
    __shared__ float4 sk[VSA_N];          // 32 KB
    __shared__ float  red[VSA_BLK / 32][9];
    __shared__ float  means[9];

    const int tid  = threadIdx.x;
    const int b    = blockIdx.y;
    const int warp = tid >> 5;
    const int lane = tid & 31;
    const int bx   = blockIdx.x;

    const float* qb = q + (size_t)b * VSA_N * 3;
    const float* kb = k + (size_t)b * VSA_N * 3;
    const float* vb = v + (size_t)b * VSA_N * 3;

    // ---- Phase A: per-batch means (block-redundant, strided over 448 thr) ----
    {
        float s[9];
#pragma unroll
        for (int c = 0; c < 9; c++) s[c] = 0.0f;

        for (int r = tid; r < VSA_N; r += VSA_BLK) {
            const int o = r * 3;
            s[0] += qb[o + 0]; s[1] += qb[o + 1]; s[2] += qb[o + 2];
            s[3] += kb[o + 0]; s[4] += kb[o + 1]; s[5] += kb[o + 2];
            s[6] += vb[o + 0]; s[7] += vb[o + 1]; s[8] += vb[o + 2];
        }
#pragma unroll
        for (int c = 0; c < 9; c++) {
#pragma unroll
            for (int off = 16; off > 0; off >>= 1)
                s[c] += __shfl_xor_sync(0xFFFFFFFFu, s[c], off);
        }
        if (lane == 0) {
#pragma unroll
            for (int c = 0; c < 9; c++) red[warp][c] = s[c];
        }
        __syncthreads();
        if (tid < 9) {
            float t = 0.0f;
#pragma unroll
            for (int w = 0; w < VSA_BLK / 32; w++) t += red[w][tid];
            means[tid] = t * (1.0f / (float)VSA_N);
        }
        __syncthreads();
    }

    const float mqx = means[0], mqy = means[1], mqz = means[2];
    const float mkx = means[3], mky = means[4], mkz = means[5];
    const float mvx = means[6], mvy = means[7], mvz = means[8];

    // c1 = log2(e) / sqrt(2048)
    const float c1 = 1.4426950408889634f * 0.022097086912079612f;

    // ---- Phase B: stage k' (re-read k; L2-hot from phase A) ----
    for (int j = tid; j < VSA_N; j += VSA_BLK) {
        const float kx = (kb[j * 3 + 0] - mkx) * c1;
        const float ky = (kb[j * 3 + 1] - mky) * c1;
        const float kz = (kb[j * 3 + 2] - mkz) * c1;
        const float kk = fmaf(kx, kx, fmaf(ky, ky, kz * kz));
        sk[j] = make_float4(kx, ky, kz, kk);
    }
    __syncthreads();

    // ---- Row assignment: blocks 0..123 get 14 rows, 124..147 get 13 ----
    const int start = bx * 13 + min(bx, 124);
    const int nrows = 13 + (bx < 124 ? 1 : 0);

    if (warp < nrows) {
        const int i = start + warp;

        const float* qi = qb + i * 3;
        const float qx = qi[0] - mqx;
        const float qy = qi[1] - mqy;
        const float qz = qi[2] - mqz;
        const float qq = fmaf(qx, qx, fmaf(qy, qy, qz * qz));

        float Z = 0.0f, Wx = 0.0f, Wy = 0.0f, Wz = 0.0f;

#pragma unroll 8
        for (int s = 0; s < VSA_N / 32; s++) {
            const float4 f = sk[s * 32 + lane];
            const float dot = fmaf(qx, f.x, fmaf(qy, f.y, qz * f.z));
            float n2 = fmaf(-dot, dot, qq * f.w);
            n2 = fmaxf(n2, 0.0f);   // cancellation can go slightly < 0
            float e;
            asm("sqrt.approx.f32 %0, %1;" : "=f"(e) : "f"(n2));
            asm("ex2.approx.f32 %0, %1;"  : "=f"(e) : "f"(e));
            Z += e;
            Wx = fmaf(e, f.x, Wx);
            Wy = fmaf(e, f.y, Wy);
            Wz = fmaf(e, f.z, Wz);
        }

        // ---- Phase D: reduce + epilogue ----
#pragma unroll
        for (int off = 16; off > 0; off >>= 1) {
            Z  += __shfl_xor_sync(0xFFFFFFFFu, Z,  off);
            Wx += __shfl_xor_sync(0xFFFFFFFFu, Wx, off);
            Wy += __shfl_xor_sync(0xFFFFFFFFu, Wy, off);
            Wz += __shfl_xor_sync(0xFFFFFFFFu, Wz, off);
        }

        if (lane == 0) {
            // T' = q x W (= c1 * T);  u = cross(T, v_c) / (Z * N)
            const float Tx = fmaf(qy, Wz, -qz * Wy);
            const float Ty = fmaf(qz, Wx, -qx * Wz);
            const float Tz = fmaf(qx, Wy, -qy * Wx);
            const float vx = vb[i * 3 + 0] - mvx;
            const float vy = vb[i * 3 + 1] - mvy;
            const float vz = vb[i * 3 + 2] - mvz;
            const float inv = 1.0f / (Z * (float)VSA_N * c1);
            float* o = out + ((size_t)b * VSA_N + i) * 3;
            o[0] = fmaf(Ty, vz, -Tz * vy) * inv;
            o[1] = fmaf(Tz, vx, -Tx * vz) * inv;
            o[2] = fmaf(Tx, vy, -Ty * vx) * inv;
        }
    }
}

// ---------------------------------------------------------------------------
extern "C" void kernel_launch(void* const* d_in, const int* in_sizes, int n_in,
                              void* d_out, int out_size) {
    const float* q = (const float*)d_in[0];
    const float* k = (const float*)d_in[1];
    const float* v = (const float*)d_in[2];
    float* out = (float*)d_out;

    const int B = out_size / (VSA_N * 3);   // = 4

    dim3 grid(VSA_BLKS_PB, B);              // (148, 4) = 592 blocks
    vsa_fused_kernel<<<grid, VSA_BLK>>>(q, k, v, out);
}